// round 12
// baseline (speedup 1.0000x reference)
#include <cuda_runtime.h>
#include <cuda_fp16.h>
#include <cstdint>

#define N_TOK 65536
#define D 256
#define K 1024
#define HW 4096
#define CAP 16

__device__ float g_sz[N_TOK];
__device__ float g_en[K];
__device__ int   g_idx[N_TOK];
__device__ __align__(16) __half g_ef[K * D];
__device__ int g_cand[N_TOK * CAP];
__device__ int g_ncand[N_TOK];
__device__ int g_flag[N_TOK];
__device__ int g_nflag;

__device__ __forceinline__ uint32_t smem_u32(const void* p) {
    uint32_t a;
    asm("{ .reg .u64 t; cvta.to.shared.u64 t, %1; cvt.u32.u64 %0, t; }" : "=r"(a) : "l"(p));
    return a;
}
__device__ __forceinline__ void cp16(uint32_t s, const void* g) {
    asm volatile("cp.async.ca.shared.global [%0], [%1], 16;" :: "r"(s), "l"(g));
}
__device__ __forceinline__ void ldm_x4(uint32_t* r, uint32_t a) {
    asm volatile("ldmatrix.sync.aligned.m8n8.x4.shared.b16 {%0,%1,%2,%3}, [%4];"
        : "=r"(r[0]), "=r"(r[1]), "=r"(r[2]), "=r"(r[3]) : "r"(a));
}
__device__ __forceinline__ void mma_f16(float* c, const uint32_t* a, const uint32_t* b) {
    asm volatile("mma.sync.aligned.m16n8k16.row.col.f32.f16.f16.f32 "
        "{%0,%1,%2,%3}, {%4,%5,%6,%7}, {%8,%9}, {%0,%1,%2,%3};"
        : "+f"(c[0]), "+f"(c[1]), "+f"(c[2]), "+f"(c[3])
        : "r"(a[0]), "r"(a[1]), "r"(a[2]), "r"(a[3]), "r"(b[0]), "r"(b[1]));
}
__device__ __forceinline__ uint32_t mono(float f) {
    uint32_t u = __float_as_uint(f);
    return (u & 0x80000000u) ? ~u : (u | 0x80000000u);
}
__device__ __forceinline__ float demono(uint32_t u) {
    return (u & 0x80000000u) ? __uint_as_float(u ^ 0x80000000u) : __uint_as_float(~u);
}

__global__ void k_init() { if (threadIdx.x == 0) g_nflag = 0; }

__global__ void k_sz(const float* __restrict__ z) {   // exact (R1-proven)
    int n = blockIdx.x * 256 + threadIdx.x;
    int b = n >> 12, hw = n & (HW - 1);
    const float* p = z + (size_t)b * D * HW + hw;
    float s = 0.f;
#pragma unroll 4
    for (int c = 0; c < D; c++) { float v = p[(size_t)c * HW]; s = fmaf(v, v, s); }
    g_sz[n] = s;
}
__global__ void k_en(const float* __restrict__ emb) { // exact (R1-proven)
    int w = (blockIdx.x * blockDim.x + threadIdx.x) >> 5;
    int lane = threadIdx.x & 31;
    const float4* row = (const float4*)(emb + (size_t)w * D);
    float s = 0.f;
#pragma unroll
    for (int i = 0; i < 2; i++) {
        float4 v = row[lane + 32 * i];
        s += v.x * v.x + v.y * v.y + v.z * v.z + v.w * v.w;
    }
#pragma unroll
    for (int o = 16; o; o >>= 1) s += __shfl_down_sync(0xFFFFFFFFu, s, o);
    if (lane == 0) g_en[w] = s;
}
__global__ void k_prep(const float* __restrict__ emb) {
    int i = blockIdx.x * 256 + threadIdx.x;
    g_ef[i] = __float2half(emb[i]);
}

// ---- pass 1: fp16 mma scores, A register-resident, sound windows -----------
// smem: BUF0 (A stage, then B even tiles) 32KB | BUF1 32KB | En | red arrays
#define BUF_SZ 32768u
#define EN_O   65536u
#define BEST_O 69632u
#define CNT_O  70144u
#define FLG_O  70400u
#define LIST_O 70656u
#define SM1    74752u

__global__ __launch_bounds__(256, 2) void k_pass1(const float* __restrict__ z) {
    extern __shared__ char sm[];
    const uint32_t sb = smem_u32(sm);
    int tid = threadIdx.x, lane = tid & 31, w = tid >> 5;
    int wm = w & 3, wn = w >> 2;           // 4 m-warps x 2 n-warps
    int gid = lane >> 2, qid = lane & 3;
    int m0 = blockIdx.x * 64;
    int bz = m0 >> 12, hw0 = m0 & (HW - 1);
    const float* zb = z + (size_t)bz * D * HW + hw0;
    float* sEn = (float*)(sm + EN_O);
    unsigned long long* sBest = (unsigned long long*)(sm + BEST_O);
    unsigned* sCnt = (unsigned*)(sm + CNT_O);
    unsigned* sFlg = (unsigned*)(sm + FLG_O);
    int* sList = (int*)(sm + LIST_O);

    for (int i = tid; i < K; i += 256) sEn[i] = g_en[i];
    if (tid < 64) { sBest[tid] = ~0ull; sCnt[tid] = 0u; sFlg[tid] = 0u; }

    // stage A fp32->fp16 into BUF0 (swizzled), then ldmatrix into registers
#pragma unroll 4
    for (int i = 0; i < 64; i++) {
        int id = i * 256 + tid;
        int d = id >> 6, r = id & 63;
        float v = zb[(size_t)d * HW + r];
        uint32_t off = (uint32_t)(r * 512 + (((d >> 3) ^ (r & 7)) * 16) + (d & 7) * 2);
        *(__half*)(sm + off) = __float2half(v);
    }
    __syncthreads();
    uint32_t a_reg[16][4];
    {
        int row = wm * 16 + (lane & 15);
        uint32_t base = (uint32_t)(row * 512);
        uint32_t rx = (uint32_t)(row & 7);
#pragma unroll
        for (int ks = 0; ks < 16; ks++)
            ldm_x4(a_reg[ks], sb + base + (uint32_t)(((ks * 2 + (lane >> 4)) ^ rx) * 16));
    }
    __syncthreads();   // BUF0 free for B staging

    auto stageB = [&](int t) {   // 64 codes x 256 dims fp16 -> buf (t&1)
        int kk = t * 64;
        uint32_t bo = sb + (uint32_t)(t & 1) * BUF_SZ;
#pragma unroll
        for (int i = 0; i < 8; i++) {
            int id = i * 256 + tid;
            int row = id >> 5, c = id & 31;
            cp16(bo + (uint32_t)(row * 512 + ((c ^ (row & 7)) * 16)),
                 g_ef + (size_t)(kk + row) * 256 + c * 8);
        }
        asm volatile("cp.async.commit_group;" ::: "memory");
    };
    stageB(0);
    stageB(1);

    float bd1[2], bd2[2]; int bk1[2], bk2[2];
#pragma unroll
    for (int i = 0; i < 2; i++) { bd1[i] = bd2[i] = 3.4e38f; bk1[i] = bk2[i] = 0; }

    // B ldmatrix addressing (constant across tiles)
    int brA = wn * 32 + ((lane >> 4) << 3) + (lane & 7);   // codes [wn*32, +16)
    int brB = brA + 16;                                     // codes [wn*32+16, +16)
    uint32_t bchunkSel = (uint32_t)((lane >> 3) & 1);

    for (int t = 0; t < 16; t++) {
        asm volatile("cp.async.wait_group 1;" ::: "memory");
        __syncthreads();
        uint32_t Bb = sb + (uint32_t)(t & 1) * BUF_SZ;
        float acc[4][4];
#pragma unroll
        for (int nt = 0; nt < 4; nt++)
#pragma unroll
            for (int c = 0; c < 4; c++) acc[nt][c] = 0.f;
#pragma unroll
        for (int ks = 0; ks < 16; ks++) {
            uint32_t bqA[4], bqB[4];
            uint32_t ch = (uint32_t)(ks * 2) + bchunkSel;
            ldm_x4(bqA, Bb + (uint32_t)(brA * 512) + (uint32_t)((ch ^ (uint32_t)(brA & 7)) * 16));
            ldm_x4(bqB, Bb + (uint32_t)(brB * 512) + (uint32_t)((ch ^ (uint32_t)(brB & 7)) * 16));
            mma_f16(acc[0], a_reg[ks], bqA + 0);
            mma_f16(acc[1], a_reg[ks], bqA + 2);
            mma_f16(acc[2], a_reg[ks], bqB + 0);
            mma_f16(acc[3], a_reg[ks], bqB + 2);
        }
#pragma unroll
        for (int nt = 0; nt < 4; nt++)
#pragma unroll
            for (int c = 0; c < 4; c++) {
                int kg = t * 64 + wn * 32 + nt * 8 + qid * 2 + (c & 1);
                float sv = fmaf(-2.f, acc[nt][c], sEn[kg]);
                int rs = c >> 1;
                if (sv < bd1[rs]) { bd2[rs] = bd1[rs]; bk2[rs] = bk1[rs];
                                    bd1[rs] = sv;      bk1[rs] = kg; }
                else if (sv < bd2[rs]) { bd2[rs] = sv; bk2[rs] = kg; }
            }
        __syncthreads();
        if (t + 2 < 16) stageB(t + 2);
    }

#pragma unroll
    for (int rs = 0; rs < 2; rs++) {
        int r = wm * 16 + gid + 8 * rs;
        unsigned long long pk = ((unsigned long long)mono(bd1[rs]) << 32) | (unsigned)bk1[rs];
        atomicMin(&sBest[r], pk);
    }
    __syncthreads();
#pragma unroll
    for (int rs = 0; rs < 2; rs++) {
        int r = wm * 16 + gid + 8 * rs;
        // sound window: 2x per-score fp16 bound (3.05e-5*||z||) + fp32 slack
        float thr = demono((uint32_t)(sBest[r] >> 32))
                  + 7e-5f * sqrtf(g_sz[m0 + r]) + 1.5e-4f;
        if (bd1[rs] <= thr) {
            unsigned o = atomicAdd(&sCnt[r], 1u);
            if (o < CAP) sList[r * CAP + o] = bk1[rs];
        }
        if (bd2[rs] <= thr) {   // thread's top-2 both in window: unsafe token
            unsigned o = atomicAdd(&sCnt[r], 1u);
            if (o < CAP) sList[r * CAP + o] = bk2[rs];
            sFlg[r] = 1u;
        }
    }
    __syncthreads();
    if (tid < 64) {
        int n = m0 + tid; unsigned nc = sCnt[tid];
        if (sFlg[tid] || nc > CAP) {
            int p = atomicAdd(&g_nflag, 1); g_flag[p] = n; g_ncand[n] = -1;
        } else {
            g_ncand[n] = (int)nc;
            for (unsigned i = 0; i < nc; i++) g_cand[n * CAP + i] = sList[tid * CAP + i];
        }
    }
}

// ---- pass 2: exact rescore of candidates (R1-proven comparator) ------------
__global__ __launch_bounds__(256) void k_rescore(const float* __restrict__ z,
                                                 const float* __restrict__ emb) {
    extern __shared__ float zs[];   // [64][257]
    int tid = threadIdx.x;
    int m0 = blockIdx.x * 64;
    int bz = m0 >> 12, hw0 = m0 & (HW - 1);
    const float* zb = z + (size_t)bz * D * HW + hw0;
#pragma unroll 4
    for (int i = 0; i < 64; i++) {
        int id = i * 256 + tid;
        int d = id >> 6, r = id & 63;
        zs[r * 257 + d] = zb[(size_t)d * HW + r];
    }
    __syncthreads();
    if (tid < 64) {
        int n = m0 + tid;
        int nc = g_ncand[n];
        if (nc >= 0) {
            float szn = g_sz[n];
            const float* zr = zs + tid * 257;
            float best = 3.4e38f; int bk = 0x7fffffff;
            for (int i = 0; i < nc; i++) {
                int k = g_cand[n * CAP + i];
                const float* er = emb + (size_t)k * D;
                float a = 0.f;
                for (int d = 0; d < D; d++) a = fmaf(zr[d], er[d], a);
                float s1 = szn + g_en[k];
                float dv = fmaf(-2.f, a, s1);
                if (dv < best || (dv == best && k < bk)) { best = dv; bk = k; }
            }
            g_idx[n] = bk;
        }
    }
}

// ---- fallback: exact full scan, 16 flagged tokens per chunk (shared emb) ---
__global__ __launch_bounds__(256) void k_fb(const float* __restrict__ z,
                                            const float* __restrict__ emb) {
    __shared__ float zt[16][257];
    __shared__ unsigned long long red[16];
    int tid = threadIdx.x;
    int nf = g_nflag;
    int nchunk = (nf + 15) >> 4;
    for (int ch = blockIdx.x; ch < nchunk; ch += gridDim.x) {
        int base = ch * 16;
        int cnt = min(16, nf - base);
        if (tid < 16) red[tid] = ~0ull;
        __syncthreads();
#pragma unroll
        for (int i = 0; i < 16; i++) {
            int id = i * 256 + tid;
            int t = id >> 8, d = id & 255;
            if (t < cnt) {
                int n = g_flag[base + t];
                int bz = n >> 12, hw = n & (HW - 1);
                zt[t][d] = z[((size_t)bz * D + d) * HW + hw];
            }
        }
        __syncthreads();
#pragma unroll
        for (int j = 0; j < 4; j++) {
            int k = tid + 256 * j;
            const float* er = emb + (size_t)k * D;
            float acc[16];
#pragma unroll
            for (int t = 0; t < 16; t++) acc[t] = 0.f;
            for (int d = 0; d < D; d++) {
                float e = er[d];
#pragma unroll
                for (int t = 0; t < 16; t++) acc[t] = fmaf(zt[t][d], e, acc[t]);
            }
            for (int t = 0; t < cnt; t++) {
                int n = g_flag[base + t];
                float s1 = g_sz[n] + g_en[k];
                float dv = fmaf(-2.f, acc[t], s1);
                unsigned long long pk =
                    ((unsigned long long)mono(dv) << 32) | (unsigned)k;
                atomicMin(&red[t], pk);
            }
        }
        __syncthreads();
        if (tid < cnt) g_idx[g_flag[base + tid]] = (int)(red[tid] & 0xffffffffu);
        __syncthreads();
    }
}

// ---- outputs ----------------------------------------------------------------
__global__ void k_out_idx(float* __restrict__ out) {
    int n = blockIdx.x * blockDim.x + threadIdx.x;
    out[n] = (float)g_idx[n];
}
__global__ void k_out_zq(const float* __restrict__ emb, float* __restrict__ out) {
    int t = blockIdx.x * blockDim.x + threadIdx.x;
    int hw = t & (HW - 1);
    int c = (t >> 12) & (D - 1);
    int b = t >> 20;
    out[t] = emb[g_idx[b * HW + hw] * D + c];
}

extern "C" void kernel_launch(void* const* d_in, const int* in_sizes, int n_in,
                              void* d_out, int out_size) {
    const float* z   = (const float*)d_in[0];
    const float* emb = (const float*)d_in[1];
    float* out = (float*)d_out;

    cudaFuncSetAttribute(k_pass1, cudaFuncAttributeMaxDynamicSharedMemorySize, SM1);
    cudaFuncSetAttribute(k_rescore, cudaFuncAttributeMaxDynamicSharedMemorySize, 64 * 257 * 4);

    k_init<<<1, 32>>>();
    k_sz<<<N_TOK / 256, 256>>>(z);
    k_en<<<K / 8, 256>>>(emb);
    k_prep<<<K * D / 256, 256>>>(emb);
    k_pass1<<<N_TOK / 64, 256, SM1>>>(z);
    k_rescore<<<N_TOK / 64, 256, 64 * 257 * 4>>>(z, emb);
    k_fb<<<128, 256>>>(z, emb);
    k_out_idx<<<N_TOK / 256, 256>>>(out);
    k_out_zq<<<(16 * D * HW) / 256, 256>>>(emb, out + N_TOK);
}

// round 13
// speedup vs baseline: 1.2692x; 1.2692x over previous
#include <cuda_runtime.h>
#include <cuda_fp16.h>
#include <cstdint>

#define N_TOK 65536
#define D 256
#define K 1024
#define HW 4096
#define CAP 16

__device__ float g_sz[N_TOK];
__device__ float g_en[K];
__device__ int   g_idx[N_TOK];
__device__ __align__(16) __half g_ef[K * D];
__device__ int g_cand[N_TOK * CAP];
__device__ int g_ncand[N_TOK];
__device__ int g_flag[N_TOK];
__device__ int g_nflag;

__device__ __forceinline__ uint32_t smem_u32(const void* p) {
    uint32_t a;
    asm("{ .reg .u64 t; cvta.to.shared.u64 t, %1; cvt.u32.u64 %0, t; }" : "=r"(a) : "l"(p));
    return a;
}
__device__ __forceinline__ void cp16(uint32_t s, const void* g) {
    asm volatile("cp.async.ca.shared.global [%0], [%1], 16;" :: "r"(s), "l"(g));
}
__device__ __forceinline__ void ldm_x4(uint32_t* r, uint32_t a) {
    asm volatile("ldmatrix.sync.aligned.m8n8.x4.shared.b16 {%0,%1,%2,%3}, [%4];"
        : "=r"(r[0]), "=r"(r[1]), "=r"(r[2]), "=r"(r[3]) : "r"(a));
}
__device__ __forceinline__ void ldm_x2(uint32_t* r, uint32_t a) {
    asm volatile("ldmatrix.sync.aligned.m8n8.x2.shared.b16 {%0,%1}, [%2];"
        : "=r"(r[0]), "=r"(r[1]) : "r"(a));
}
__device__ __forceinline__ void mma_f16(float* c, const uint32_t* a, const uint32_t* b) {
    asm volatile("mma.sync.aligned.m16n8k16.row.col.f32.f16.f16.f32 "
        "{%0,%1,%2,%3}, {%4,%5,%6,%7}, {%8,%9}, {%0,%1,%2,%3};"
        : "+f"(c[0]), "+f"(c[1]), "+f"(c[2]), "+f"(c[3])
        : "r"(a[0]), "r"(a[1]), "r"(a[2]), "r"(a[3]), "r"(b[0]), "r"(b[1]));
}
__device__ __forceinline__ uint32_t mono(float f) {
    uint32_t u = __float_as_uint(f);
    return (u & 0x80000000u) ? ~u : (u | 0x80000000u);
}
__device__ __forceinline__ float demono(uint32_t u) {
    return (u & 0x80000000u) ? __uint_as_float(u ^ 0x80000000u) : __uint_as_float(~u);
}

__global__ void k_init() { if (threadIdx.x == 0) g_nflag = 0; }

__global__ void k_sz(const float* __restrict__ z) {   // exact (R1-proven)
    int n = blockIdx.x * 256 + threadIdx.x;
    int b = n >> 12, hw = n & (HW - 1);
    const float* p = z + (size_t)b * D * HW + hw;
    float s = 0.f;
#pragma unroll 4
    for (int c = 0; c < D; c++) { float v = p[(size_t)c * HW]; s = fmaf(v, v, s); }
    g_sz[n] = s;
}
__global__ void k_en(const float* __restrict__ emb) { // exact (R1-proven)
    int w = (blockIdx.x * blockDim.x + threadIdx.x) >> 5;
    int lane = threadIdx.x & 31;
    const float4* row = (const float4*)(emb + (size_t)w * D);
    float s = 0.f;
#pragma unroll
    for (int i = 0; i < 2; i++) {
        float4 v = row[lane + 32 * i];
        s += v.x * v.x + v.y * v.y + v.z * v.z + v.w * v.w;
    }
#pragma unroll
    for (int o = 16; o; o >>= 1) s += __shfl_down_sync(0xFFFFFFFFu, s, o);
    if (lane == 0) g_en[w] = s;
}
__global__ void k_prep(const float* __restrict__ emb) {
    int i = blockIdx.x * 256 + threadIdx.x;
    g_ef[i] = __float2half(emb[i]);
}

// ---- pass 1: fp16 mma scores, register-pipelined fragments -----------------
#define A_O    0u
#define B_O    32768u
#define EN_O   98304u
#define BEST_O 102400u
#define CNT_O  102912u
#define FLG_O  103168u
#define LIST_O 103424u
#define SM1    107520u

__global__ __launch_bounds__(256) void k_pass1(const float* __restrict__ z) {
    extern __shared__ char sm[];
    const uint32_t sb = smem_u32(sm);
    int tid = threadIdx.x, lane = tid & 31, w = tid >> 5;
    int wm = w & 1, wn = w >> 1, gid = lane >> 2, qid = lane & 3;
    int m0 = blockIdx.x * 64;
    int bz = m0 >> 12, hw0 = m0 & (HW - 1);
    const float* zb = z + (size_t)bz * D * HW + hw0;
    float* sEn = (float*)(sm + EN_O);
    unsigned long long* sBest = (unsigned long long*)(sm + BEST_O);
    unsigned* sCnt = (unsigned*)(sm + CNT_O);
    unsigned* sFlg = (unsigned*)(sm + FLG_O);
    int* sList = (int*)(sm + LIST_O);

    for (int i = tid; i < K; i += 256) sEn[i] = g_en[i];
    if (tid < 64) { sBest[tid] = ~0ull; sCnt[tid] = 0u; sFlg[tid] = 0u; }
    // stage A: 64 tokens x 256 dims fp16 (full-K resident, swizzled)
#pragma unroll 4
    for (int i = 0; i < 64; i++) {
        int id = i * 256 + tid;
        int d = id >> 6, r = id & 63;
        float v = zb[(size_t)d * HW + r];
        uint32_t off = (uint32_t)(r * 512 + (((d >> 3) ^ (r & 7)) * 16) + (d & 7) * 2);
        *(__half*)(sm + A_O + off) = __float2half(v);
    }
    auto stageB = [&](int t, int buf) {   // 64 codes x 256 dims fp16
        int kk = t * 64;
#pragma unroll
        for (int i = 0; i < 8; i++) {
            int id = i * 256 + tid;
            int row = id >> 5, c = id & 31;
            cp16(sb + B_O + (uint32_t)buf * 32768u +
                     (uint32_t)(row * 512 + ((c ^ (row & 7)) * 16)),
                 g_ef + (size_t)(kk + row) * 256 + c * 8);
        }
        asm volatile("cp.async.commit_group;" ::: "memory");
    };
    stageB(0, 0);
    __syncthreads();

    // per-warp constant fragment addressing
    int arow0 = wm * 32 + (lane & 15);
    int arow1 = arow0 + 16;
    uint32_t aBase0 = sb + A_O + (uint32_t)(arow0 * 512);
    uint32_t aBase1 = sb + A_O + (uint32_t)(arow1 * 512);
    uint32_t arx0 = (uint32_t)(arow0 & 7), arx1 = (uint32_t)(arow1 & 7);
    uint32_t aSel = (uint32_t)(lane >> 4);
    int brow0 = wn * 16 + (lane & 7);
    int brow1 = brow0 + 8;
    uint32_t brx0 = (uint32_t)(brow0 & 7), brx1 = (uint32_t)(brow1 & 7);
    uint32_t bSel = (uint32_t)((lane >> 3) & 1);

    float bd1[4], bd2[4]; int bk1[4], bk2[4];
#pragma unroll
    for (int i = 0; i < 4; i++) { bd1[i] = bd2[i] = 3.4e38f; bk1[i] = bk2[i] = 0; }

    for (int t = 0; t < 16; t++) {
        if (t < 15) { stageB(t + 1, (t + 1) & 1);
                      asm volatile("cp.async.wait_group 1;" ::: "memory"); }
        else        { asm volatile("cp.async.wait_group 0;" ::: "memory"); }
        __syncthreads();
        uint32_t Bb = sb + B_O + (uint32_t)(t & 1) * 32768u;
        uint32_t bBase0 = Bb + (uint32_t)(brow0 * 512);
        uint32_t bBase1 = Bb + (uint32_t)(brow1 * 512);

        float acc[2][2][4];
#pragma unroll
        for (int mt = 0; mt < 2; mt++)
#pragma unroll
            for (int nt = 0; nt < 2; nt++)
#pragma unroll
                for (int c = 0; c < 4; c++) acc[mt][nt][c] = 0.f;

        // register double-buffered fragments: load ks+1 while mma on ks
        uint32_t af[2][2][4], bf[2][2][2];
        {
            uint32_t ch = aSel;                       // ks=0
            ldm_x4(af[0][0], aBase0 + ((ch ^ arx0) * 16));
            ldm_x4(af[0][1], aBase1 + ((ch ^ arx1) * 16));
            uint32_t cb = bSel;
            ldm_x2(bf[0][0], bBase0 + ((cb ^ brx0) * 16));
            ldm_x2(bf[0][1], bBase1 + ((cb ^ brx1) * 16));
        }
#pragma unroll
        for (int ks = 0; ks < 16; ks++) {
            int cur = ks & 1, nxt = cur ^ 1;
            if (ks < 15) {
                uint32_t ch = (uint32_t)((ks + 1) * 2) + aSel;
                ldm_x4(af[nxt][0], aBase0 + ((ch ^ arx0) * 16));
                ldm_x4(af[nxt][1], aBase1 + ((ch ^ arx1) * 16));
                uint32_t cb = (uint32_t)((ks + 1) * 2) + bSel;
                ldm_x2(bf[nxt][0], bBase0 + ((cb ^ brx0) * 16));
                ldm_x2(bf[nxt][1], bBase1 + ((cb ^ brx1) * 16));
            }
#pragma unroll
            for (int mt = 0; mt < 2; mt++)
#pragma unroll
                for (int nt = 0; nt < 2; nt++)
                    mma_f16(acc[mt][nt], af[cur][mt], bf[cur][nt]);
        }
#pragma unroll
        for (int mt = 0; mt < 2; mt++)
#pragma unroll
            for (int nt = 0; nt < 2; nt++)
#pragma unroll
                for (int c = 0; c < 4; c++) {
                    int kg = t * 64 + wn * 16 + nt * 8 + qid * 2 + (c & 1);
                    float sv = fmaf(-2.f, acc[mt][nt][c], sEn[kg]);
                    int rs = mt * 2 + (c >> 1);
                    if (sv < bd1[rs]) { bd2[rs] = bd1[rs]; bk2[rs] = bk1[rs];
                                        bd1[rs] = sv;      bk1[rs] = kg; }
                    else if (sv < bd2[rs]) { bd2[rs] = sv; bk2[rs] = kg; }
                }
        __syncthreads();
    }
#pragma unroll
    for (int rs = 0; rs < 4; rs++) {
        int r = wm * 32 + (rs >> 1) * 16 + gid + 8 * (rs & 1);
        unsigned long long pk = ((unsigned long long)mono(bd1[rs]) << 32) | (unsigned)bk1[rs];
        atomicMin(&sBest[r], pk);
    }
    __syncthreads();
#pragma unroll
    for (int rs = 0; rs < 4; rs++) {
        int r = wm * 32 + (rs >> 1) * 16 + gid + 8 * (rs & 1);
        // sound window: 2x per-score fp16 bound (3.05e-5*||z||) + fp32 slack
        float thr = demono((uint32_t)(sBest[r] >> 32))
                  + 7e-5f * sqrtf(g_sz[m0 + r]) + 1.5e-4f;
        if (bd1[rs] <= thr) {
            unsigned o = atomicAdd(&sCnt[r], 1u);
            if (o < CAP) sList[r * CAP + o] = bk1[rs];
        }
        if (bd2[rs] <= thr) {   // thread's top-2 both in window: unsafe token
            unsigned o = atomicAdd(&sCnt[r], 1u);
            if (o < CAP) sList[r * CAP + o] = bk2[rs];
            sFlg[r] = 1u;
        }
    }
    __syncthreads();
    if (tid < 64) {
        int n = m0 + tid; unsigned nc = sCnt[tid];
        if (sFlg[tid] || nc > CAP) {
            int p = atomicAdd(&g_nflag, 1); g_flag[p] = n; g_ncand[n] = -1;
        } else {
            g_ncand[n] = (int)nc;
            for (unsigned i = 0; i < nc; i++) g_cand[n * CAP + i] = sList[tid * CAP + i];
        }
    }
}

// ---- pass 2: exact rescore of candidates (R1-proven comparator) ------------
__global__ __launch_bounds__(256) void k_rescore(const float* __restrict__ z,
                                                 const float* __restrict__ emb) {
    extern __shared__ float zs[];   // [64][257]
    int tid = threadIdx.x;
    int m0 = blockIdx.x * 64;
    int bz = m0 >> 12, hw0 = m0 & (HW - 1);
    const float* zb = z + (size_t)bz * D * HW + hw0;
#pragma unroll 4
    for (int i = 0; i < 64; i++) {
        int id = i * 256 + tid;
        int d = id >> 6, r = id & 63;
        zs[r * 257 + d] = zb[(size_t)d * HW + r];
    }
    __syncthreads();
    if (tid < 64) {
        int n = m0 + tid;
        int nc = g_ncand[n];
        if (nc >= 0) {
            float szn = g_sz[n];
            const float* zr = zs + tid * 257;
            float best = 3.4e38f; int bk = 0x7fffffff;
            for (int i = 0; i < nc; i++) {
                int k = g_cand[n * CAP + i];
                const float* er = emb + (size_t)k * D;
                float a = 0.f;
                for (int d = 0; d < D; d++) a = fmaf(zr[d], er[d], a);
                float s1 = szn + g_en[k];
                float dv = fmaf(-2.f, a, s1);
                if (dv < best || (dv == best && k < bk)) { best = dv; bk = k; }
            }
            g_idx[n] = bk;
        }
    }
}

// ---- fallback: exact full scan, 16 flagged tokens per chunk (shared emb) ---
__global__ __launch_bounds__(256) void k_fb(const float* __restrict__ z,
                                            const float* __restrict__ emb) {
    __shared__ float zt[16][257];
    __shared__ unsigned long long red[16];
    int tid = threadIdx.x;
    int nf = g_nflag;
    int nchunk = (nf + 15) >> 4;
    for (int ch = blockIdx.x; ch < nchunk; ch += gridDim.x) {
        int base = ch * 16;
        int cnt = min(16, nf - base);
        if (tid < 16) red[tid] = ~0ull;
        __syncthreads();
#pragma unroll
        for (int i = 0; i < 16; i++) {
            int id = i * 256 + tid;
            int t = id >> 8, d = id & 255;
            if (t < cnt) {
                int n = g_flag[base + t];
                int bz = n >> 12, hw = n & (HW - 1);
                zt[t][d] = z[((size_t)bz * D + d) * HW + hw];
            }
        }
        __syncthreads();
#pragma unroll
        for (int j = 0; j < 4; j++) {
            int k = tid + 256 * j;
            const float* er = emb + (size_t)k * D;
            float acc[16];
#pragma unroll
            for (int t = 0; t < 16; t++) acc[t] = 0.f;
            for (int d = 0; d < D; d++) {
                float e = er[d];
#pragma unroll
                for (int t = 0; t < 16; t++) acc[t] = fmaf(zt[t][d], e, acc[t]);
            }
            for (int t = 0; t < cnt; t++) {
                int n = g_flag[base + t];
                float s1 = g_sz[n] + g_en[k];
                float dv = fmaf(-2.f, acc[t], s1);
                unsigned long long pk =
                    ((unsigned long long)mono(dv) << 32) | (unsigned)k;
                atomicMin(&red[t], pk);
            }
        }
        __syncthreads();
        if (tid < cnt) g_idx[g_flag[base + tid]] = (int)(red[tid] & 0xffffffffu);
        __syncthreads();
    }
}

// ---- outputs ----------------------------------------------------------------
__global__ void k_out_idx(float* __restrict__ out) {
    int n = blockIdx.x * blockDim.x + threadIdx.x;
    out[n] = (float)g_idx[n];
}
__global__ void k_out_zq(const float* __restrict__ emb, float* __restrict__ out) {
    int t = blockIdx.x * blockDim.x + threadIdx.x;
    int hw = t & (HW - 1);
    int c = (t >> 12) & (D - 1);
    int b = t >> 20;
    out[t] = emb[g_idx[b * HW + hw] * D + c];
}

extern "C" void kernel_launch(void* const* d_in, const int* in_sizes, int n_in,
                              void* d_out, int out_size) {
    const float* z   = (const float*)d_in[0];
    const float* emb = (const float*)d_in[1];
    float* out = (float*)d_out;

    cudaFuncSetAttribute(k_pass1, cudaFuncAttributeMaxDynamicSharedMemorySize, SM1);
    cudaFuncSetAttribute(k_rescore, cudaFuncAttributeMaxDynamicSharedMemorySize, 64 * 257 * 4);

    k_init<<<1, 32>>>();
    k_sz<<<N_TOK / 256, 256>>>(z);
    k_en<<<K / 8, 256>>>(emb);
    k_prep<<<K * D / 256, 256>>>(emb);
    k_pass1<<<N_TOK / 64, 256, SM1>>>(z);
    k_rescore<<<N_TOK / 64, 256, 64 * 257 * 4>>>(z, emb);
    k_fb<<<128, 256>>>(z, emb);
    k_out_idx<<<N_TOK / 256, 256>>>(out);
    k_out_zq<<<(16 * D * HW) / 256, 256>>>(emb, out + N_TOK);
}